// round 15
// baseline (speedup 1.0000x reference)
#include <cuda_runtime.h>
#include <cuda_bf16.h>
#include <cstdint>
#include <math.h>

static constexpr int B_  = 4;
static constexpr int S_  = 2048;
static constexpr int D_  = 1024;
static constexpr int H_  = 16;
static constexpr int DK_ = 64;
static constexpr int M_  = B_ * S_;   // 8192 rows

// ---------------------------------------------------------------------------
// Scratch (allocation-free rule: __device__ globals)
// ---------------------------------------------------------------------------
__device__ __nv_bfloat16 g_AH[3][(size_t)M_ * D_];  // q,k,v activation hi
__device__ __nv_bfloat16 g_AL[3][(size_t)M_ * D_];  // q,k,v activation lo
__device__ __nv_bfloat16 g_WH[4][(size_t)D_ * D_];  // Wq,Wk,Wv,Wo hi
__device__ __nv_bfloat16 g_WL[4][(size_t)D_ * D_];  // Wq,Wk,Wv,Wo lo
__device__ __nv_bfloat16 g_PH[3][(size_t)M_ * D_];  // Q,K,V projected hi [B,H,S,DK]
__device__ __nv_bfloat16 g_PL[3][(size_t)M_ * D_];  // Q,K,V projected lo
__device__ __nv_bfloat16 g_CH[(size_t)M_ * D_];     // ctx hi [B,S,H*DK]
__device__ __nv_bfloat16 g_CL[(size_t)M_ * D_];     // ctx lo

// ---------------------------------------------------------------------------
// Warp-MMA helpers (base sm_80 features — valid on plain sm_103 PTX target)
// ---------------------------------------------------------------------------
__device__ __forceinline__ uint32_t smem_u32(const void* p) {
    uint32_t a;
    asm("{ .reg .u64 t; cvta.to.shared.u64 t, %1; cvt.u32.u64 %0, t; }"
        : "=r"(a) : "l"(p));
    return a;
}

__device__ __forceinline__ void cp16(uint32_t dst, const void* src) {
    asm volatile("cp.async.cg.shared.global [%0], [%1], 16;"
                 :: "r"(dst), "l"(src));
}
#define CP_COMMIT() asm volatile("cp.async.commit_group;" ::: "memory")
#define CP_WAIT(N)  asm volatile("cp.async.wait_group %0;" :: "n"(N) : "memory")

__device__ __forceinline__ void ldsm4(uint32_t* r, uint32_t addr) {
    asm volatile("ldmatrix.sync.aligned.m8n8.x4.shared.b16 {%0,%1,%2,%3}, [%4];"
                 : "=r"(r[0]), "=r"(r[1]), "=r"(r[2]), "=r"(r[3]) : "r"(addr));
}
__device__ __forceinline__ void ldsm4t(uint32_t* r, uint32_t addr) {
    asm volatile("ldmatrix.sync.aligned.m8n8.x4.trans.shared.b16 {%0,%1,%2,%3}, [%4];"
                 : "=r"(r[0]), "=r"(r[1]), "=r"(r[2]), "=r"(r[3]) : "r"(addr));
}

__device__ __forceinline__ void mma16816(float* c, const uint32_t* a,
                                         const uint32_t* b) {
    asm volatile(
        "mma.sync.aligned.m16n8k16.row.col.f32.bf16.bf16.f32 "
        "{%0,%1,%2,%3}, {%4,%5,%6,%7}, {%8,%9}, {%0,%1,%2,%3};"
        : "+f"(c[0]), "+f"(c[1]), "+f"(c[2]), "+f"(c[3])
        : "r"(a[0]), "r"(a[1]), "r"(a[2]), "r"(a[3]), "r"(b[0]), "r"(b[1]));
}

__device__ __forceinline__ uint32_t sw128(uint32_t b) { return b ^ ((b >> 3) & 0x70); }

__device__ __forceinline__ uint32_t pack2_hi(float c0, float c1) {
    __nv_bfloat162 p = __halves2bfloat162(__float2bfloat16(c0), __float2bfloat16(c1));
    return *(uint32_t*)&p;
}
__device__ __forceinline__ uint32_t pack2_lo(float c0, float c1, uint32_t hipack) {
    __nv_bfloat162 hp = *(__nv_bfloat162*)&hipack;
    __nv_bfloat162 p  = __halves2bfloat162(
        __float2bfloat16(c0 - __bfloat162float(hp.x)),
        __float2bfloat16(c1 - __bfloat162float(hp.y)));
    return *(uint32_t*)&p;
}

// ---------------------------------------------------------------------------
// Split fp32 -> bf16 hi + lo. Merged launches: activations (z=0..2), weights (z=0..3).
// ---------------------------------------------------------------------------
__device__ __forceinline__ void split_one(const float* __restrict__ x,
                                          __nv_bfloat16* __restrict__ hi,
                                          __nv_bfloat16* __restrict__ lo,
                                          int i)
{
    float4 v = ((const float4*)x)[i];
    uint32_t h0 = pack2_hi(v.x, v.y);
    uint32_t h1 = pack2_hi(v.z, v.w);
    uint32_t l0 = pack2_lo(v.x, v.y, h0);
    uint32_t l1 = pack2_lo(v.z, v.w, h1);
    ((uint32_t*)hi)[2 * i + 0] = h0;
    ((uint32_t*)hi)[2 * i + 1] = h1;
    ((uint32_t*)lo)[2 * i + 0] = l0;
    ((uint32_t*)lo)[2 * i + 1] = l1;
}

__global__ __launch_bounds__(256) void split_act(const float* __restrict__ q,
                                                 const float* __restrict__ k,
                                                 const float* __restrict__ v)
{
    int z = blockIdx.z;
    const float* src = (z == 0) ? q : (z == 1) ? k : v;
    int i = blockIdx.x * blockDim.x + threadIdx.x;
    split_one(src, g_AH[z], g_AL[z], i);
}

__global__ __launch_bounds__(256) void split_w(const float* __restrict__ wq,
                                               const float* __restrict__ wk,
                                               const float* __restrict__ wv,
                                               const float* __restrict__ wo)
{
    int z = blockIdx.z;
    const float* src = (z == 0) ? wq : (z == 1) ? wk : (z == 2) ? wv : wo;
    int i = blockIdx.x * blockDim.x + threadIdx.x;
    split_one(src, g_WH[z], g_WL[z], i);
}

// ---------------------------------------------------------------------------
// bf16x3 GEMM mainloop (unchanged from best config): CTA 64x128, 4 warps,
// K-chunk 64, 2-stage cp.async, one barrier per chunk.
// ---------------------------------------------------------------------------
static constexpr int GA_T      = 8192;             // A tile 64x64 bf16
static constexpr int GB_T      = 16384;            // B tile 128x64 bf16
static constexpr int G_STAGE   = 2 * GA_T + 2 * GB_T;   // 48 KB
static constexpr int SMEM_GEMM = 2 * G_STAGE;           // 96 KB

__device__ __forceinline__ void gemm_mainloop(
    const uint4* __restrict__ gAh, const uint4* __restrict__ gAl,
    const uint4* __restrict__ gWh, const uint4* __restrict__ gWl,
    int m0, int n0, uint32_t sb, float c[4][4][4])
{
    const int tid  = threadIdx.x;
    const int lane = tid & 31;
    const int wid  = tid >> 5;        // 0..3 = n quarter

    const int a_r = lane & 15;
    const int a_c = (lane >> 4) * 16;
    const int b_r = wid * 32 + (lane & 7) + ((lane >> 4) << 3);
    const int b_c = ((lane >> 3) & 1) * 16;

#pragma unroll
    for (int i = 0; i < 4; i++)
#pragma unroll
        for (int j = 0; j < 4; j++)
#pragma unroll
            for (int e = 0; e < 4; e++) c[i][j][e] = 0.f;

    auto load_chunk = [&](int kc, int stage) {
        const uint32_t sbase = sb + stage * G_STAGE;
#pragma unroll
        for (int u = 0; u < 8; u++) {
            int fi   = u * 128 + tid;        // 0..1023
            int tile = fi >> 9;              // 0=Ahi 1=Alo
            int e    = fi & 511;
            int row  = e >> 3;               // 0..63
            int j    = e & 7;
            uint32_t dst = sbase + tile * GA_T + sw128(row * 128 + j * 16);
            size_t gi = (size_t)(m0 + row) * 128 + kc * 8 + j;
            cp16(dst, (tile == 0 ? gAh : gAl) + gi);
        }
#pragma unroll
        for (int u = 0; u < 16; u++) {
            int fi   = u * 128 + tid;        // 0..2047
            int tile = fi >> 10;             // 0=Bhi 1=Blo
            int e    = fi & 1023;
            int row  = e >> 3;               // 0..127
            int j    = e & 7;
            uint32_t dst = sbase + 2 * GA_T + tile * GB_T + sw128(row * 128 + j * 16);
            size_t gi = (size_t)(n0 + row) * 128 + kc * 8 + j;
            cp16(dst, (tile == 0 ? gWh : gWl) + gi);
        }
    };

    load_chunk(0, 0); CP_COMMIT();

    for (int kc = 0; kc < 16; kc++) {
        CP_WAIT(0);
        __syncthreads();
        if (kc + 1 < 16) { load_chunk(kc + 1, (kc + 1) & 1); CP_COMMIT(); }

        const uint32_t st  = sb + (kc & 1) * G_STAGE;
        const uint32_t sAh = st;
        const uint32_t sAl = st + GA_T;
        const uint32_t sBh = st + 2 * GA_T;
        const uint32_t sBl = st + 2 * GA_T + GB_T;

#pragma unroll
        for (int ks = 0; ks < 4; ks++) {
            uint32_t bh[4][2], bl[4][2];
#pragma unroll
            for (int nt2 = 0; nt2 < 2; nt2++) {
                uint32_t off = sw128((uint32_t)(b_r + nt2 * 16) * 128 + ks * 32 + b_c);
                uint32_t t[4];
                ldsm4(t, sBh + off);
                bh[2 * nt2][0] = t[0]; bh[2 * nt2][1] = t[1];
                bh[2 * nt2 + 1][0] = t[2]; bh[2 * nt2 + 1][1] = t[3];
                ldsm4(t, sBl + off);
                bl[2 * nt2][0] = t[0]; bl[2 * nt2][1] = t[1];
                bl[2 * nt2 + 1][0] = t[2]; bl[2 * nt2 + 1][1] = t[3];
            }
#pragma unroll
            for (int mt = 0; mt < 4; mt++) {
                uint32_t off = sw128((uint32_t)(a_r + mt * 16) * 128 + ks * 32 + a_c);
                uint32_t ah[4], al[4];
                ldsm4(ah, sAh + off);
                ldsm4(al, sAl + off);
#pragma unroll
                for (int nt = 0; nt < 4; nt++) mma16816(c[mt][nt], ah, bh[nt]);
#pragma unroll
                for (int nt = 0; nt < 4; nt++) mma16816(c[mt][nt], ah, bl[nt]);
#pragma unroll
                for (int nt = 0; nt < 4; nt++) mma16816(c[mt][nt], al, bh[nt]);
            }
        }
    }
}

// ---- QKV projections in one launch: grid (8, 128, 3) ----
__global__ __launch_bounds__(128, 2)
void gemm_qkv()
{
    extern __shared__ __align__(1024) char smem[];
    const uint32_t sb = smem_u32(smem);
    const int z  = blockIdx.z;
    const int n0 = blockIdx.x * 128;
    const int m0 = blockIdx.y * 64;
    // Q: fold 1/sqrt(dk)=0.125 AND log2(e) (for exp2-based softmax) into scale
    const float scale = (z == 0) ? 0.125f * 1.44269504f : 1.0f;

    float c[4][4][4];
    gemm_mainloop((const uint4*)g_AH[z], (const uint4*)g_AL[z],
                  (const uint4*)g_WH[z], (const uint4*)g_WL[z],
                  m0, n0, sb, c);

    const int lane = threadIdx.x & 31;
    const int wid  = threadIdx.x >> 5;
    __nv_bfloat16* Yhi = g_PH[z];
    __nv_bfloat16* Ylo = g_PL[z];

#pragma unroll
    for (int mt = 0; mt < 4; mt++) {
#pragma unroll
        for (int half = 0; half < 2; half++) {
            int r  = m0 + mt * 16 + (lane >> 2) + half * 8;
            int bb = r >> 11;
            int s  = r & (S_ - 1);
#pragma unroll
            for (int nt = 0; nt < 4; nt++) {
                int e  = n0 + wid * 32 + nt * 8 + (lane & 3) * 2;
                int h  = e >> 6;
                int dk = e & 63;
                float v0 = c[mt][nt][2 * half + 0] * scale;
                float v1 = c[mt][nt][2 * half + 1] * scale;
                size_t idx = (((size_t)bb * H_ + h) * S_ + s) * DK_ + dk;
                uint32_t hp = pack2_hi(v0, v1);
                uint32_t lp = pack2_lo(v0, v1, hp);
                *(uint32_t*)&Yhi[idx] = hp;
                *(uint32_t*)&Ylo[idx] = lp;
            }
        }
    }
}

// ---- Output projection: ctx @ Wo^T -> fp32 out ----
__global__ __launch_bounds__(128, 2)
void gemm_out(float* __restrict__ Y)
{
    extern __shared__ __align__(1024) char smem[];
    const uint32_t sb = smem_u32(smem);
    const int n0 = blockIdx.x * 128;
    const int m0 = blockIdx.y * 64;

    float c[4][4][4];
    gemm_mainloop((const uint4*)g_CH, (const uint4*)g_CL,
                  (const uint4*)g_WH[3], (const uint4*)g_WL[3],
                  m0, n0, sb, c);

    const int lane = threadIdx.x & 31;
    const int wid  = threadIdx.x >> 5;

#pragma unroll
    for (int mt = 0; mt < 4; mt++) {
#pragma unroll
        for (int half = 0; half < 2; half++) {
            int r = m0 + mt * 16 + (lane >> 2) + half * 8;
#pragma unroll
            for (int nt = 0; nt < 4; nt++) {
                int e = n0 + wid * 32 + nt * 8 + (lane & 3) * 2;
                size_t idx = (size_t)r * D_ + e;
                *(float2*)&Y[idx] = make_float2(c[mt][nt][2 * half + 0],
                                                c[mt][nt][2 * half + 1]);
            }
        }
    }
}

// ---------------------------------------------------------------------------
// Tensor-core causal flash attention (bf16x3, fp32-accurate), software-
// pipelined across key blocks: iteration kb computes PV(kb) INTERLEAVED with
// QK(kb+1) — independent accumulators (o vs sc) give the tensor pipe two
// dependency-free MMA streams. K double-buffered (read 1 block ahead),
// V triple-buffered. smem = 16K(Q) + 32K(K) + 48K(V) = 96KB => 2 CTAs/SM.
// No-max softmax in base-2 (log2e pre-folded into Q).
// ---------------------------------------------------------------------------
static constexpr int FA_T    = 8192;                 // one 64x64 bf16 matrix
static constexpr int FA_KB0  = 2 * FA_T;             // K stages base (16KB)
static constexpr int FA_VB0  = FA_KB0 + 2 * 2 * FA_T;   // V stages base (48KB)
static constexpr int SMEM_FA = FA_VB0 + 3 * 2 * FA_T;   // 98304 (96KB)

__global__ __launch_bounds__(128, 2)
void flash_mma()
{
    extern __shared__ __align__(1024) char smem[];
    const uint32_t sb = smem_u32(smem);

    const int tid  = threadIdx.x;
    const int lane = tid & 31;
    const int wid  = tid >> 5;
    const int qb   = (gridDim.x - 1) - blockIdx.x;   // heavy tiles first
    const int bh   = blockIdx.y;

    const size_t head4 = (size_t)bh * S_ * DK_ / 8;
    const uint4* q4h = (const uint4*)g_PH[0] + head4;
    const uint4* q4l = (const uint4*)g_PL[0] + head4;
    const uint4* k4h = (const uint4*)g_PH[1] + head4;
    const uint4* k4l = (const uint4*)g_PL[1] + head4;
    const uint4* v4h = (const uint4*)g_PH[2] + head4;
    const uint4* v4l = (const uint4*)g_PL[2] + head4;

    auto load_q = [&]() {
#pragma unroll
        for (int u = 0; u < 8; u++) {
            int fi   = u * 128 + tid;
            int tile = fi >> 9;              // 0=hi 1=lo
            int e    = fi & 511;
            int row  = e >> 3;
            int j    = e & 7;
            uint32_t dst = sb + tile * FA_T + sw128(row * 128 + j * 16);
            size_t gi = (size_t)(qb * 64 + row) * 8 + j;
            cp16(dst, (tile == 0 ? q4h : q4l) + gi);
        }
    };
    auto load_k = [&](int kb, int st) {
#pragma unroll
        for (int u = 0; u < 8; u++) {
            int fi   = u * 128 + tid;
            int tile = fi >> 9;
            int e    = fi & 511;
            int row  = e >> 3;
            int j    = e & 7;
            uint32_t dst = sb + FA_KB0 + st * 2 * FA_T + tile * FA_T
                         + sw128(row * 128 + j * 16);
            size_t gi = (size_t)(kb * 64 + row) * 8 + j;
            cp16(dst, (tile == 0 ? k4h : k4l) + gi);
        }
    };
    auto load_v = [&](int kb, int st) {
#pragma unroll
        for (int u = 0; u < 8; u++) {
            int fi   = u * 128 + tid;
            int tile = fi >> 9;
            int e    = fi & 511;
            int row  = e >> 3;
            int j    = e & 7;
            uint32_t dst = sb + FA_VB0 + st * 2 * FA_T + tile * FA_T
                         + sw128(row * 128 + j * 16);
            size_t gi = (size_t)(kb * 64 + row) * 8 + j;
            cp16(dst, (tile == 0 ? v4h : v4l) + gi);
        }
    };

    const int nkb = qb + 1;

    // prologue: Q + block0, then block1
    load_q(); load_k(0, 0); load_v(0, 0); CP_COMMIT();
    if (nkb > 1) { load_k(1, 1); load_v(1, 1); }
    CP_COMMIT();

    // fragment addressing
    const int a_r  = wid * 16 + (lane & 15);
    const int a_c  = (lane >> 4) * 16;
    const int b_r  = (lane & 7) + ((lane >> 4) << 3);
    const int b_c  = ((lane >> 3) & 1) * 16;
    const int vt_r = ((lane >> 3) & 1) * 8 + (lane & 7);
    const int vt_c = (lane >> 4) * 16;
    const uint32_t sQh = sb;
    const uint32_t sQl = sb + FA_T;

    float o[8][4];
#pragma unroll
    for (int nt = 0; nt < 8; nt++)
#pragma unroll
        for (int e = 0; e < 4; e++) o[nt][e] = 0.f;
    float l0 = 0.f, l1 = 0.f;
    float sc[8][4];
    uint32_t ph[8][2], pl[8][2];

    const int row_g0 = qb * 64 + wid * 16 + (lane >> 2);

    // ---- QK for one key block (standalone) ----
    auto do_qk = [&](int stK) {
        const uint32_t sKh = sb + FA_KB0 + stK * 2 * FA_T;
        const uint32_t sKl = sKh + FA_T;
#pragma unroll
        for (int nt = 0; nt < 8; nt++)
#pragma unroll
            for (int e = 0; e < 4; e++) sc[nt][e] = 0.f;
#pragma unroll
        for (int ks = 0; ks < 4; ks++) {
            uint32_t aoff = sw128((uint32_t)a_r * 128 + ks * 32 + a_c);
            uint32_t ah[4], al[4];
            ldsm4(ah, sQh + aoff);
            ldsm4(al, sQl + aoff);
            uint32_t th[4][4], tl[4][4];
#pragma unroll
            for (int nt2 = 0; nt2 < 4; nt2++) {
                uint32_t boff = sw128((uint32_t)(b_r + nt2 * 16) * 128 + ks * 32 + b_c);
                ldsm4(th[nt2], sKh + boff);
                ldsm4(tl[nt2], sKl + boff);
            }
#pragma unroll
            for (int nt2 = 0; nt2 < 4; nt2++) {
                mma16816(sc[2 * nt2 + 0], ah, th[nt2] + 0);
                mma16816(sc[2 * nt2 + 1], ah, th[nt2] + 2);
            }
#pragma unroll
            for (int nt2 = 0; nt2 < 4; nt2++) {
                mma16816(sc[2 * nt2 + 0], ah, tl[nt2] + 0);
                mma16816(sc[2 * nt2 + 1], ah, tl[nt2] + 2);
            }
#pragma unroll
            for (int nt2 = 0; nt2 < 4; nt2++) {
                mma16816(sc[2 * nt2 + 0], al, th[nt2] + 0);
                mma16816(sc[2 * nt2 + 1], al, th[nt2] + 2);
            }
        }
    };

    // ---- PV for one key block (standalone) ----
    auto do_pv = [&](int stV) {
        const uint32_t sVh = sb + FA_VB0 + stV * 2 * FA_T;
        const uint32_t sVl = sVh + FA_T;
#pragma unroll
        for (int ks = 0; ks < 4; ks++) {
            uint32_t pah[4] = {ph[2 * ks][0], ph[2 * ks][1],
                               ph[2 * ks + 1][0], ph[2 * ks + 1][1]};
            uint32_t pal[4] = {pl[2 * ks][0], pl[2 * ks][1],
                               pl[2 * ks + 1][0], pl[2 * ks + 1][1]};
            uint32_t tvh[4][4], tvl[4][4];
#pragma unroll
            for (int nt2 = 0; nt2 < 4; nt2++) {
                uint32_t voff = sw128((uint32_t)(ks * 16 + vt_r) * 128 + nt2 * 32 + vt_c);
                ldsm4t(tvh[nt2], sVh + voff);
                ldsm4t(tvl[nt2], sVl + voff);
            }
#pragma unroll
            for (int nt2 = 0; nt2 < 4; nt2++) {
                mma16816(o[2 * nt2 + 0], pah, tvh[nt2] + 0);
                mma16816(o[2 * nt2 + 1], pah, tvh[nt2] + 2);
            }
#pragma unroll
            for (int nt2 = 0; nt2 < 4; nt2++) {
                mma16816(o[2 * nt2 + 0], pah, tvl[nt2] + 0);
                mma16816(o[2 * nt2 + 1], pah, tvl[nt2] + 2);
            }
#pragma unroll
            for (int nt2 = 0; nt2 < 4; nt2++) {
                mma16816(o[2 * nt2 + 0], pal, tvh[nt2] + 0);
                mma16816(o[2 * nt2 + 1], pal, tvh[nt2] + 2);
            }
        }
    };

    // ---- interleaved: QK(next block, stage stK) + PV(current, stage stV) ----
    auto do_qkpv = [&](int stK, int stV) {
        const uint32_t sKh = sb + FA_KB0 + stK * 2 * FA_T;
        const uint32_t sKl = sKh + FA_T;
        const uint32_t sVh = sb + FA_VB0 + stV * 2 * FA_T;
        const uint32_t sVl = sVh + FA_T;
#pragma unroll
        for (int nt = 0; nt < 8; nt++)
#pragma unroll
            for (int e = 0; e < 4; e++) sc[nt][e] = 0.f;
#pragma unroll
        for (int ks = 0; ks < 4; ks++) {
            // --- QK stream (writes sc) ---
            uint32_t aoff = sw128((uint32_t)a_r * 128 + ks * 32 + a_c);
            uint32_t ah[4], al[4];
            ldsm4(ah, sQh + aoff);
            ldsm4(al, sQl + aoff);
            uint32_t th[4][4], tl[4][4];
#pragma unroll
            for (int nt2 = 0; nt2 < 4; nt2++) {
                uint32_t boff = sw128((uint32_t)(b_r + nt2 * 16) * 128 + ks * 32 + b_c);
                ldsm4(th[nt2], sKh + boff);
                ldsm4(tl[nt2], sKl + boff);
            }
            // --- PV stream operands (writes o) ---
            uint32_t pah[4] = {ph[2 * ks][0], ph[2 * ks][1],
                               ph[2 * ks + 1][0], ph[2 * ks + 1][1]};
            uint32_t pal[4] = {pl[2 * ks][0], pl[2 * ks][1],
                               pl[2 * ks + 1][0], pl[2 * ks + 1][1]};
            uint32_t tvh[4][4], tvl[4][4];
#pragma unroll
            for (int nt2 = 0; nt2 < 4; nt2++) {
                uint32_t voff = sw128((uint32_t)(ks * 16 + vt_r) * 128 + nt2 * 32 + vt_c);
                ldsm4t(tvh[nt2], sVh + voff);
                ldsm4t(tvl[nt2], sVl + voff);
            }
            // --- interleave the two independent MMA streams ---
#pragma unroll
            for (int nt2 = 0; nt2 < 4; nt2++) {
                mma16816(sc[2 * nt2 + 0], ah, th[nt2] + 0);
                mma16816(o[2 * nt2 + 0], pah, tvh[nt2] + 0);
                mma16816(sc[2 * nt2 + 1], ah, th[nt2] + 2);
                mma16816(o[2 * nt2 + 1], pah, tvh[nt2] + 2);
            }
#pragma unroll
            for (int nt2 = 0; nt2 < 4; nt2++) {
                mma16816(sc[2 * nt2 + 0], ah, tl[nt2] + 0);
                mma16816(o[2 * nt2 + 0], pah, tvl[nt2] + 0);
                mma16816(sc[2 * nt2 + 1], ah, tl[nt2] + 2);
                mma16816(o[2 * nt2 + 1], pah, tvl[nt2] + 2);
            }
#pragma unroll
            for (int nt2 = 0; nt2 < 4; nt2++) {
                mma16816(sc[2 * nt2 + 0], al, th[nt2] + 0);
                mma16816(o[2 * nt2 + 0], pal, tvh[nt2] + 0);
                mma16816(sc[2 * nt2 + 1], al, th[nt2] + 2);
                mma16816(o[2 * nt2 + 1], pal, tvh[nt2] + 2);
            }
        }
    };

    // ---- softmax (no-max, base-2) + causal mask + pack P to bf16 hi/lo ----
    auto do_smax_pack = [&](int kbt) {
        if (kbt == qb) {
#pragma unroll
            for (int nt = 0; nt < 8; nt++) {
                int col = kbt * 64 + nt * 8 + 2 * (lane & 3);
                if (col     > row_g0)     sc[nt][0] = -1e30f;
                if (col + 1 > row_g0)     sc[nt][1] = -1e30f;
                if (col     > row_g0 + 8) sc[nt][2] = -1e30f;
                if (col + 1 > row_g0 + 8) sc[nt][3] = -1e30f;
            }
        }
#pragma unroll
        for (int nt = 0; nt < 8; nt++) {
            sc[nt][0] = exp2f(sc[nt][0]);
            sc[nt][1] = exp2f(sc[nt][1]);
            sc[nt][2] = exp2f(sc[nt][2]);
            sc[nt][3] = exp2f(sc[nt][3]);
        }
        float a0 = 0.f, a1 = 0.f, b0 = 0.f, b1 = 0.f;
#pragma unroll
        for (int nt = 0; nt < 8; nt += 2) {
            a0 += sc[nt][0] + sc[nt][1];
            a1 += sc[nt + 1][0] + sc[nt + 1][1];
            b0 += sc[nt][2] + sc[nt][3];
            b1 += sc[nt + 1][2] + sc[nt + 1][3];
        }
        float rs0 = a0 + a1;
        float rs1 = b0 + b1;
        rs0 += __shfl_xor_sync(0xffffffffu, rs0, 1);
        rs0 += __shfl_xor_sync(0xffffffffu, rs0, 2);
        rs1 += __shfl_xor_sync(0xffffffffu, rs1, 1);
        rs1 += __shfl_xor_sync(0xffffffffu, rs1, 2);
        l0 += rs0;
        l1 += rs1;
#pragma unroll
        for (int nt = 0; nt < 8; nt++) {
            ph[nt][0] = pack2_hi(sc[nt][0], sc[nt][1]);
            ph[nt][1] = pack2_hi(sc[nt][2], sc[nt][3]);
            pl[nt][0] = pack2_lo(sc[nt][0], sc[nt][1], ph[nt][0]);
            pl[nt][1] = pack2_lo(sc[nt][2], sc[nt][3], ph[nt][1]);
        }
    };

    // ---- steady state ----
    CP_WAIT(1);            // Q + block0 landed
    __syncthreads();
    do_qk(0);
    do_smax_pack(0);

    for (int kb = 0; kb < nkb; kb++) {
        CP_WAIT(0);        // all loads up to block kb+1 landed
        __syncthreads();   // fences compute kb-1; freed stages reusable
        if (kb + 2 < nkb) {
            load_k(kb + 2, (kb + 2) & 1);
            load_v(kb + 2, (kb + 2) % 3);
            CP_COMMIT();
        }
        if (kb + 1 < nkb) {
            do_qkpv((kb + 1) & 1, kb % 3);   // QK(kb+1) + PV(kb) interleaved
            do_smax_pack(kb + 1);
        } else {
            do_pv(kb % 3);                   // final block: PV only
        }
    }

    // ---- epilogue: ctx[b, s, h*64+dk] as bf16 hi/lo ----
    const int bb = bh >> 4;
    const int h  = bh & (H_ - 1);
    const float inv0 = 1.f / l0;
    const float inv1 = 1.f / l1;
    const int s0r = qb * 64 + wid * 16 + (lane >> 2);
#pragma unroll
    for (int nt = 0; nt < 8; nt++) {
        int dk = nt * 8 + 2 * (lane & 3);
        {
            float v0 = o[nt][0] * inv0, v1 = o[nt][1] * inv0;
            size_t idx = ((size_t)bb * S_ + s0r) * D_ + h * 64 + dk;
            uint32_t hp = pack2_hi(v0, v1);
            uint32_t lp = pack2_lo(v0, v1, hp);
            *(uint32_t*)&g_CH[idx] = hp;
            *(uint32_t*)&g_CL[idx] = lp;
        }
        {
            float v0 = o[nt][2] * inv1, v1 = o[nt][3] * inv1;
            size_t idx = ((size_t)bb * S_ + s0r + 8) * D_ + h * 64 + dk;
            uint32_t hp = pack2_hi(v0, v1);
            uint32_t lp = pack2_lo(v0, v1, hp);
            *(uint32_t*)&g_CH[idx] = hp;
            *(uint32_t*)&g_CL[idx] = lp;
        }
    }
}

// ---------------------------------------------------------------------------
extern "C" void kernel_launch(void* const* d_in, const int* in_sizes, int n_in,
                              void* d_out, int out_size)
{
    const float* q  = (const float*)d_in[0];
    const float* k  = (const float*)d_in[1];
    const float* v  = (const float*)d_in[2];
    const float* Wq = (const float*)d_in[3];
    const float* Wk = (const float*)d_in[4];
    const float* Wv = (const float*)d_in[5];
    const float* Wo = (const float*)d_in[6];
    // d_in[7] = causal tril mask; applied analytically in flash_mma.
    float* out = (float*)d_out;

    cudaFuncSetAttribute(gemm_qkv, cudaFuncAttributeMaxDynamicSharedMemorySize, SMEM_GEMM);
    cudaFuncSetAttribute(gemm_out, cudaFuncAttributeMaxDynamicSharedMemorySize, SMEM_GEMM);
    cudaFuncSetAttribute(flash_mma, cudaFuncAttributeMaxDynamicSharedMemorySize, SMEM_FA);

    // 1. split all inputs to bf16 hi/lo
    split_act<<<dim3(M_ * D_ / 4 / 256, 1, 3), 256>>>(q, k, v);
    split_w<<<dim3(D_ * D_ / 4 / 256, 1, 4), 256>>>(Wq, Wk, Wv, Wo);

    // 2. Q/K/V projections in one launch (3072 CTAs, 2/SM)
    gemm_qkv<<<dim3(D_ / 128, M_ / 64, 3), 128, SMEM_GEMM>>>();

    // 3. causal flash attention (2048 CTAs, 2/SM, block-pipelined)
    flash_mma<<<dim3(S_ / 64, B_ * H_), 128, SMEM_FA>>>();

    // 4. output projection
    gemm_out<<<dim3(D_ / 128, M_ / 64), 128, SMEM_GEMM>>>(out);
}

// round 16
// speedup vs baseline: 1.0043x; 1.0043x over previous
#include <cuda_runtime.h>
#include <cuda_bf16.h>
#include <cstdint>
#include <math.h>

static constexpr int B_  = 4;
static constexpr int S_  = 2048;
static constexpr int D_  = 1024;
static constexpr int H_  = 16;
static constexpr int DK_ = 64;
static constexpr int M_  = B_ * S_;   // 8192 rows

// ---------------------------------------------------------------------------
// Scratch (allocation-free rule: __device__ globals)
// ---------------------------------------------------------------------------
__device__ __nv_bfloat16 g_AH[3][(size_t)M_ * D_];  // q,k,v activation hi
__device__ __nv_bfloat16 g_AL[3][(size_t)M_ * D_];  // q,k,v activation lo
__device__ __nv_bfloat16 g_WH[4][(size_t)D_ * D_];  // Wq,Wk,Wv,Wo hi
__device__ __nv_bfloat16 g_WL[4][(size_t)D_ * D_];  // Wq,Wk,Wv,Wo lo
__device__ __nv_bfloat16 g_PH[3][(size_t)M_ * D_];  // Q,K,V projected hi [B,H,S,DK]
__device__ __nv_bfloat16 g_PL[3][(size_t)M_ * D_];  // Q,K,V projected lo
__device__ __nv_bfloat16 g_CH[(size_t)M_ * D_];     // ctx hi [B,S,H*DK]
__device__ __nv_bfloat16 g_CL[(size_t)M_ * D_];     // ctx lo

// ---------------------------------------------------------------------------
// Warp-MMA helpers (base sm_80 features — valid on plain sm_103 PTX target)
// ---------------------------------------------------------------------------
__device__ __forceinline__ uint32_t smem_u32(const void* p) {
    uint32_t a;
    asm("{ .reg .u64 t; cvta.to.shared.u64 t, %1; cvt.u32.u64 %0, t; }"
        : "=r"(a) : "l"(p));
    return a;
}

__device__ __forceinline__ void cp16(uint32_t dst, const void* src) {
    asm volatile("cp.async.cg.shared.global [%0], [%1], 16;"
                 :: "r"(dst), "l"(src));
}
#define CP_COMMIT() asm volatile("cp.async.commit_group;" ::: "memory")
#define CP_WAIT(N)  asm volatile("cp.async.wait_group %0;" :: "n"(N) : "memory")

__device__ __forceinline__ void ldsm4(uint32_t* r, uint32_t addr) {
    asm volatile("ldmatrix.sync.aligned.m8n8.x4.shared.b16 {%0,%1,%2,%3}, [%4];"
                 : "=r"(r[0]), "=r"(r[1]), "=r"(r[2]), "=r"(r[3]) : "r"(addr));
}
__device__ __forceinline__ void ldsm4t(uint32_t* r, uint32_t addr) {
    asm volatile("ldmatrix.sync.aligned.m8n8.x4.trans.shared.b16 {%0,%1,%2,%3}, [%4];"
                 : "=r"(r[0]), "=r"(r[1]), "=r"(r[2]), "=r"(r[3]) : "r"(addr));
}

__device__ __forceinline__ void mma16816(float* c, const uint32_t* a,
                                         const uint32_t* b) {
    asm volatile(
        "mma.sync.aligned.m16n8k16.row.col.f32.bf16.bf16.f32 "
        "{%0,%1,%2,%3}, {%4,%5,%6,%7}, {%8,%9}, {%0,%1,%2,%3};"
        : "+f"(c[0]), "+f"(c[1]), "+f"(c[2]), "+f"(c[3])
        : "r"(a[0]), "r"(a[1]), "r"(a[2]), "r"(a[3]), "r"(b[0]), "r"(b[1]));
}

__device__ __forceinline__ uint32_t sw128(uint32_t b) { return b ^ ((b >> 3) & 0x70); }

__device__ __forceinline__ uint32_t pack2_hi(float c0, float c1) {
    __nv_bfloat162 p = __halves2bfloat162(__float2bfloat16(c0), __float2bfloat16(c1));
    return *(uint32_t*)&p;
}
__device__ __forceinline__ uint32_t pack2_lo(float c0, float c1, uint32_t hipack) {
    __nv_bfloat162 hp = *(__nv_bfloat162*)&hipack;
    __nv_bfloat162 p  = __halves2bfloat162(
        __float2bfloat16(c0 - __bfloat162float(hp.x)),
        __float2bfloat16(c1 - __bfloat162float(hp.y)));
    return *(uint32_t*)&p;
}

// ---------------------------------------------------------------------------
// Split fp32 -> bf16 hi + lo. Merged launches: activations (z=0..2), weights (z=0..3).
// ---------------------------------------------------------------------------
__device__ __forceinline__ void split_one(const float* __restrict__ x,
                                          __nv_bfloat16* __restrict__ hi,
                                          __nv_bfloat16* __restrict__ lo,
                                          int i)
{
    float4 v = ((const float4*)x)[i];
    uint32_t h0 = pack2_hi(v.x, v.y);
    uint32_t h1 = pack2_hi(v.z, v.w);
    uint32_t l0 = pack2_lo(v.x, v.y, h0);
    uint32_t l1 = pack2_lo(v.z, v.w, h1);
    ((uint32_t*)hi)[2 * i + 0] = h0;
    ((uint32_t*)hi)[2 * i + 1] = h1;
    ((uint32_t*)lo)[2 * i + 0] = l0;
    ((uint32_t*)lo)[2 * i + 1] = l1;
}

__global__ __launch_bounds__(256) void split_act(const float* __restrict__ q,
                                                 const float* __restrict__ k,
                                                 const float* __restrict__ v)
{
    int z = blockIdx.z;
    const float* src = (z == 0) ? q : (z == 1) ? k : v;
    int i = blockIdx.x * blockDim.x + threadIdx.x;
    split_one(src, g_AH[z], g_AL[z], i);
}

__global__ __launch_bounds__(256) void split_w(const float* __restrict__ wq,
                                               const float* __restrict__ wk,
                                               const float* __restrict__ wv,
                                               const float* __restrict__ wo)
{
    int z = blockIdx.z;
    const float* src = (z == 0) ? wq : (z == 1) ? wk : (z == 2) ? wv : wo;
    int i = blockIdx.x * blockDim.x + threadIdx.x;
    split_one(src, g_WH[z], g_WL[z], i);
}

// ---------------------------------------------------------------------------
// bf16x3 GEMM mainloop (R12 best form): CTA 64x128, 4 warps, K-chunk 64,
// 2-stage cp.async, load-before-wait + trailing barrier.
// ---------------------------------------------------------------------------
static constexpr int GA_T      = 8192;             // A tile 64x64 bf16
static constexpr int GB_T      = 16384;            // B tile 128x64 bf16
static constexpr int G_STAGE   = 2 * GA_T + 2 * GB_T;   // 48 KB
static constexpr int SMEM_GEMM = 2 * G_STAGE;           // 96 KB

__device__ __forceinline__ void gemm_mainloop(
    const uint4* __restrict__ gAh, const uint4* __restrict__ gAl,
    const uint4* __restrict__ gWh, const uint4* __restrict__ gWl,
    int m0, int n0, uint32_t sb, float c[4][4][4])
{
    const int tid  = threadIdx.x;
    const int lane = tid & 31;
    const int wid  = tid >> 5;        // 0..3 = n quarter

    const int a_r = lane & 15;
    const int a_c = (lane >> 4) * 16;
    const int b_r = wid * 32 + (lane & 7) + ((lane >> 4) << 3);
    const int b_c = ((lane >> 3) & 1) * 16;

#pragma unroll
    for (int i = 0; i < 4; i++)
#pragma unroll
        for (int j = 0; j < 4; j++)
#pragma unroll
            for (int e = 0; e < 4; e++) c[i][j][e] = 0.f;

    auto load_chunk = [&](int kc, int stage) {
        const uint32_t sbase = sb + stage * G_STAGE;
#pragma unroll
        for (int u = 0; u < 8; u++) {
            int fi   = u * 128 + tid;        // 0..1023
            int tile = fi >> 9;              // 0=Ahi 1=Alo
            int e    = fi & 511;
            int row  = e >> 3;               // 0..63
            int j    = e & 7;
            uint32_t dst = sbase + tile * GA_T + sw128(row * 128 + j * 16);
            size_t gi = (size_t)(m0 + row) * 128 + kc * 8 + j;
            cp16(dst, (tile == 0 ? gAh : gAl) + gi);
        }
#pragma unroll
        for (int u = 0; u < 16; u++) {
            int fi   = u * 128 + tid;        // 0..2047
            int tile = fi >> 10;             // 0=Bhi 1=Blo
            int e    = fi & 1023;
            int row  = e >> 3;               // 0..127
            int j    = e & 7;
            uint32_t dst = sbase + 2 * GA_T + tile * GB_T + sw128(row * 128 + j * 16);
            size_t gi = (size_t)(n0 + row) * 128 + kc * 8 + j;
            cp16(dst, (tile == 0 ? gWh : gWl) + gi);
        }
    };

    load_chunk(0, 0); CP_COMMIT();

    for (int kc = 0; kc < 16; kc++) {
        if (kc < 15) { load_chunk(kc + 1, (kc + 1) & 1); CP_COMMIT(); CP_WAIT(1); }
        else         { CP_WAIT(0); }
        __syncthreads();

        const uint32_t st  = sb + (kc & 1) * G_STAGE;
        const uint32_t sAh = st;
        const uint32_t sAl = st + GA_T;
        const uint32_t sBh = st + 2 * GA_T;
        const uint32_t sBl = st + 2 * GA_T + GB_T;

#pragma unroll
        for (int ks = 0; ks < 4; ks++) {
            uint32_t bh[4][2], bl[4][2];
#pragma unroll
            for (int nt2 = 0; nt2 < 2; nt2++) {
                uint32_t off = sw128((uint32_t)(b_r + nt2 * 16) * 128 + ks * 32 + b_c);
                uint32_t t[4];
                ldsm4(t, sBh + off);
                bh[2 * nt2][0] = t[0]; bh[2 * nt2][1] = t[1];
                bh[2 * nt2 + 1][0] = t[2]; bh[2 * nt2 + 1][1] = t[3];
                ldsm4(t, sBl + off);
                bl[2 * nt2][0] = t[0]; bl[2 * nt2][1] = t[1];
                bl[2 * nt2 + 1][0] = t[2]; bl[2 * nt2 + 1][1] = t[3];
            }
#pragma unroll
            for (int mt = 0; mt < 4; mt++) {
                uint32_t off = sw128((uint32_t)(a_r + mt * 16) * 128 + ks * 32 + a_c);
                uint32_t ah[4], al[4];
                ldsm4(ah, sAh + off);
                ldsm4(al, sAl + off);
#pragma unroll
                for (int nt = 0; nt < 4; nt++) mma16816(c[mt][nt], ah, bh[nt]);
#pragma unroll
                for (int nt = 0; nt < 4; nt++) mma16816(c[mt][nt], ah, bl[nt]);
#pragma unroll
                for (int nt = 0; nt < 4; nt++) mma16816(c[mt][nt], al, bh[nt]);
            }
        }
        __syncthreads();   // all warps done before this stage is overwritten
    }
}

// ---- QKV projections in one launch: grid (8, 128, 3) ----
__global__ __launch_bounds__(128, 2)
void gemm_qkv()
{
    extern __shared__ __align__(1024) char smem[];
    const uint32_t sb = smem_u32(smem);
    const int z  = blockIdx.z;
    const int n0 = blockIdx.x * 128;
    const int m0 = blockIdx.y * 64;
    // Q: fold 1/sqrt(dk)=0.125 AND log2(e) (for exp2-based softmax) into scale
    const float scale = (z == 0) ? 0.125f * 1.44269504f : 1.0f;

    float c[4][4][4];
    gemm_mainloop((const uint4*)g_AH[z], (const uint4*)g_AL[z],
                  (const uint4*)g_WH[z], (const uint4*)g_WL[z],
                  m0, n0, sb, c);

    const int lane = threadIdx.x & 31;
    const int wid  = threadIdx.x >> 5;
    __nv_bfloat16* Yhi = g_PH[z];
    __nv_bfloat16* Ylo = g_PL[z];

#pragma unroll
    for (int mt = 0; mt < 4; mt++) {
#pragma unroll
        for (int half = 0; half < 2; half++) {
            int r  = m0 + mt * 16 + (lane >> 2) + half * 8;
            int bb = r >> 11;
            int s  = r & (S_ - 1);
#pragma unroll
            for (int nt = 0; nt < 4; nt++) {
                int e  = n0 + wid * 32 + nt * 8 + (lane & 3) * 2;
                int h  = e >> 6;
                int dk = e & 63;
                float v0 = c[mt][nt][2 * half + 0] * scale;
                float v1 = c[mt][nt][2 * half + 1] * scale;
                size_t idx = (((size_t)bb * H_ + h) * S_ + s) * DK_ + dk;
                uint32_t hp = pack2_hi(v0, v1);
                uint32_t lp = pack2_lo(v0, v1, hp);
                *(uint32_t*)&Yhi[idx] = hp;
                *(uint32_t*)&Ylo[idx] = lp;
            }
        }
    }
}

// ---- Output projection: ctx @ Wo^T -> fp32 out ----
__global__ __launch_bounds__(128, 2)
void gemm_out(float* __restrict__ Y)
{
    extern __shared__ __align__(1024) char smem[];
    const uint32_t sb = smem_u32(smem);
    const int n0 = blockIdx.x * 128;
    const int m0 = blockIdx.y * 64;

    float c[4][4][4];
    gemm_mainloop((const uint4*)g_CH, (const uint4*)g_CL,
                  (const uint4*)g_WH[3], (const uint4*)g_WL[3],
                  m0, n0, sb, c);

    const int lane = threadIdx.x & 31;
    const int wid  = threadIdx.x >> 5;

#pragma unroll
    for (int mt = 0; mt < 4; mt++) {
#pragma unroll
        for (int half = 0; half < 2; half++) {
            int r = m0 + mt * 16 + (lane >> 2) + half * 8;
#pragma unroll
            for (int nt = 0; nt < 4; nt++) {
                int e = n0 + wid * 32 + nt * 8 + (lane & 3) * 2;
                size_t idx = (size_t)r * D_ + e;
                *(float2*)&Y[idx] = make_float2(c[mt][nt][2 * half + 0],
                                                c[mt][nt][2 * half + 1]);
            }
        }
    }
}

// ---------------------------------------------------------------------------
// Tensor-core causal flash attention (bf16x3, fp32-accurate).
// CTA = 128 queries, 4 warps x 32 query rows (fat warp M-tile: halves the
// redundant K/V ldsm traffic per query — MMA/ldsm ratio 2.6 -> 4.8), key
// blocks of 64, 2-stage KV pipeline, one barrier per block. smem = 32K(Q) +
// 2x32K(KV) = 96KB => 2 CTAs/SM. No-max base-2 softmax (log2e folded in Q).
// P packed to bf16 hi/lo on the fly per k16 chunk (no persistent P arrays).
// ---------------------------------------------------------------------------
static constexpr int FA_T     = 8192;                // one 64x64 bf16 matrix
static constexpr int FA_Q     = 2 * 16384;           // Q 128x64 hi+lo = 32KB
static constexpr int FA_STAGE = 4 * FA_T;            // Khi,Klo,Vhi,Vlo = 32KB
static constexpr int SMEM_FA  = FA_Q + 2 * FA_STAGE; // 98304 (96KB)

__global__ __launch_bounds__(128, 2)
void flash_mma()
{
    extern __shared__ __align__(1024) char smem[];
    const uint32_t sb = smem_u32(smem);

    const int tid  = threadIdx.x;
    const int lane = tid & 31;
    const int wid  = tid >> 5;
    const int qb   = (gridDim.x - 1) - blockIdx.x;   // heavy tiles first
    const int bh   = blockIdx.y;

    const size_t head4 = (size_t)bh * S_ * DK_ / 8;
    const uint4* q4h = (const uint4*)g_PH[0] + head4;
    const uint4* q4l = (const uint4*)g_PL[0] + head4;
    const uint4* k4h = (const uint4*)g_PH[1] + head4;
    const uint4* k4l = (const uint4*)g_PL[1] + head4;
    const uint4* v4h = (const uint4*)g_PH[2] + head4;
    const uint4* v4l = (const uint4*)g_PL[2] + head4;

    // ---- Q tile (128 x 64 bf16, hi+lo = 2048 uint4, 16/thread) ----
#pragma unroll
    for (int u = 0; u < 16; u++) {
        int fi   = u * 128 + tid;        // 0..2047
        int tile = fi >> 10;             // 0=hi 1=lo
        int e    = fi & 1023;
        int row  = e >> 3;               // 0..127
        int j    = e & 7;
        uint32_t dst = sb + tile * 16384 + sw128(row * 128 + j * 16);
        size_t gi = (size_t)(qb * 128 + row) * 8 + j;
        cp16(dst, (tile == 0 ? q4h : q4l) + gi);
    }

    auto load_kv = [&](int kb, int st) {
        const uint32_t sbase = sb + FA_Q + st * FA_STAGE;
#pragma unroll
        for (int u = 0; u < 16; u++) {
            int fi   = u * 128 + tid;     // 0..2047
            int tile = fi >> 9;           // 0=Khi 1=Klo 2=Vhi 3=Vlo
            int e    = fi & 511;
            int row  = e >> 3;
            int j    = e & 7;
            uint32_t dst = sbase + tile * FA_T + sw128(row * 128 + j * 16);
            size_t gi = (size_t)(kb * 64 + row) * 8 + j;
            const uint4* src = (tile == 0) ? k4h : (tile == 1) ? k4l :
                               (tile == 2) ? v4h : v4l;
            cp16(dst, src + gi);
        }
    };

    const int nkb = 2 * qb + 2;
    load_kv(0, 0); CP_COMMIT();

    // fragment addressing: warp owns rows [wid*32, wid*32+32)
    const int a_r0 = wid * 32 + (lane & 15);
    const int a_c  = (lane >> 4) * 16;
    const int b_r  = (lane & 7) + ((lane >> 4) << 3);
    const int b_c  = ((lane >> 3) & 1) * 16;
    const int vt_r = ((lane >> 3) & 1) * 8 + (lane & 7);
    const int vt_c = (lane >> 4) * 16;
    const uint32_t sQh = sb;
    const uint32_t sQl = sb + 16384;

    float o[2][8][4];
#pragma unroll
    for (int mt = 0; mt < 2; mt++)
#pragma unroll
        for (int nt = 0; nt < 8; nt++)
#pragma unroll
            for (int e = 0; e < 4; e++) o[mt][nt][e] = 0.f;
    float lsum[2][2] = {{0.f, 0.f}, {0.f, 0.f}};

    const int row_b = qb * 128 + wid * 32 + (lane >> 2);   // + mt*16 (+8)

    for (int kb = 0; kb < nkb; kb++) {
        CP_WAIT(0);
        __syncthreads();       // fences kb-1 compute; stage (kb+1)&1 now free
        if (kb + 1 < nkb) { load_kv(kb + 1, (kb + 1) & 1); CP_COMMIT(); }

        const uint32_t st  = sb + FA_Q + (kb & 1) * FA_STAGE;
        const uint32_t sKh = st;
        const uint32_t sKl = st + FA_T;
        const uint32_t sVh = st + 2 * FA_T;
        const uint32_t sVl = st + 3 * FA_T;

        // ---- scores: 32 rows x 64 keys per warp ----
        float sc[2][8][4];
#pragma unroll
        for (int mt = 0; mt < 2; mt++)
#pragma unroll
            for (int nt = 0; nt < 8; nt++)
#pragma unroll
                for (int e = 0; e < 4; e++) sc[mt][nt][e] = 0.f;

#pragma unroll
        for (int ks = 0; ks < 4; ks++) {
            uint32_t ah[2][4], al[2][4];
#pragma unroll
            for (int mt = 0; mt < 2; mt++) {
                uint32_t aoff = sw128((uint32_t)(a_r0 + mt * 16) * 128 + ks * 32 + a_c);
                ldsm4(ah[mt], sQh + aoff);
                ldsm4(al[mt], sQl + aoff);
            }
            uint32_t th[4][4], tl[4][4];
#pragma unroll
            for (int nt2 = 0; nt2 < 4; nt2++) {
                uint32_t boff = sw128((uint32_t)(b_r + nt2 * 16) * 128 + ks * 32 + b_c);
                ldsm4(th[nt2], sKh + boff);
                ldsm4(tl[nt2], sKl + boff);
            }
#pragma unroll
            for (int mt = 0; mt < 2; mt++)
#pragma unroll
                for (int nt2 = 0; nt2 < 4; nt2++) {
                    mma16816(sc[mt][2 * nt2 + 0], ah[mt], th[nt2] + 0);
                    mma16816(sc[mt][2 * nt2 + 1], ah[mt], th[nt2] + 2);
                }
#pragma unroll
            for (int mt = 0; mt < 2; mt++)
#pragma unroll
                for (int nt2 = 0; nt2 < 4; nt2++) {
                    mma16816(sc[mt][2 * nt2 + 0], ah[mt], tl[nt2] + 0);
                    mma16816(sc[mt][2 * nt2 + 1], ah[mt], tl[nt2] + 2);
                }
#pragma unroll
            for (int mt = 0; mt < 2; mt++)
#pragma unroll
                for (int nt2 = 0; nt2 < 4; nt2++) {
                    mma16816(sc[mt][2 * nt2 + 0], al[mt], th[nt2] + 0);
                    mma16816(sc[mt][2 * nt2 + 1], al[mt], th[nt2] + 2);
                }
        }

        // ---- causal mask (diagonal key blocks): exp2(-1e30) = 0 ----
        if (kb >= 2 * qb) {
#pragma unroll
            for (int mt = 0; mt < 2; mt++) {
                int rg = row_b + mt * 16;
#pragma unroll
                for (int nt = 0; nt < 8; nt++) {
                    int col = kb * 64 + nt * 8 + 2 * (lane & 3);
                    if (col     > rg)     sc[mt][nt][0] = -1e30f;
                    if (col + 1 > rg)     sc[mt][nt][1] = -1e30f;
                    if (col     > rg + 8) sc[mt][nt][2] = -1e30f;
                    if (col + 1 > rg + 8) sc[mt][nt][3] = -1e30f;
                }
            }
        }

        // ---- softmax: p = exp2(s) (log2e pre-folded into Q); tree sums ----
#pragma unroll
        for (int mt = 0; mt < 2; mt++) {
#pragma unroll
            for (int nt = 0; nt < 8; nt++) {
                sc[mt][nt][0] = exp2f(sc[mt][nt][0]);
                sc[mt][nt][1] = exp2f(sc[mt][nt][1]);
                sc[mt][nt][2] = exp2f(sc[mt][nt][2]);
                sc[mt][nt][3] = exp2f(sc[mt][nt][3]);
            }
            float a0 = 0.f, a1 = 0.f, b0 = 0.f, b1 = 0.f;
#pragma unroll
            for (int nt = 0; nt < 8; nt += 2) {
                a0 += sc[mt][nt][0] + sc[mt][nt][1];
                a1 += sc[mt][nt + 1][0] + sc[mt][nt + 1][1];
                b0 += sc[mt][nt][2] + sc[mt][nt][3];
                b1 += sc[mt][nt + 1][2] + sc[mt][nt + 1][3];
            }
            float rs0 = a0 + a1;
            float rs1 = b0 + b1;
            rs0 += __shfl_xor_sync(0xffffffffu, rs0, 1);
            rs0 += __shfl_xor_sync(0xffffffffu, rs0, 2);
            rs1 += __shfl_xor_sync(0xffffffffu, rs1, 1);
            rs1 += __shfl_xor_sync(0xffffffffu, rs1, 2);
            lsum[mt][0] += rs0;
            lsum[mt][1] += rs1;
        }

        // ---- O += P @ V  (P packed on the fly per k16 chunk) ----
#pragma unroll
        for (int ks = 0; ks < 4; ks++) {
            uint32_t tvh[4][4], tvl[4][4];
#pragma unroll
            for (int nt2 = 0; nt2 < 4; nt2++) {
                uint32_t voff = sw128((uint32_t)(ks * 16 + vt_r) * 128 + nt2 * 32 + vt_c);
                ldsm4t(tvh[nt2], sVh + voff);
                ldsm4t(tvl[nt2], sVl + voff);
            }
#pragma unroll
            for (int mt = 0; mt < 2; mt++) {
                uint32_t pah[4], pal[4];
                pah[0] = pack2_hi(sc[mt][2 * ks][0],     sc[mt][2 * ks][1]);
                pah[1] = pack2_hi(sc[mt][2 * ks][2],     sc[mt][2 * ks][3]);
                pah[2] = pack2_hi(sc[mt][2 * ks + 1][0], sc[mt][2 * ks + 1][1]);
                pah[3] = pack2_hi(sc[mt][2 * ks + 1][2], sc[mt][2 * ks + 1][3]);
                pal[0] = pack2_lo(sc[mt][2 * ks][0],     sc[mt][2 * ks][1],     pah[0]);
                pal[1] = pack2_lo(sc[mt][2 * ks][2],     sc[mt][2 * ks][3],     pah[1]);
                pal[2] = pack2_lo(sc[mt][2 * ks + 1][0], sc[mt][2 * ks + 1][1], pah[2]);
                pal[3] = pack2_lo(sc[mt][2 * ks + 1][2], sc[mt][2 * ks + 1][3], pah[3]);
#pragma unroll
                for (int nt2 = 0; nt2 < 4; nt2++) {
                    mma16816(o[mt][2 * nt2 + 0], pah, tvh[nt2] + 0);
                    mma16816(o[mt][2 * nt2 + 1], pah, tvh[nt2] + 2);
                }
#pragma unroll
                for (int nt2 = 0; nt2 < 4; nt2++) {
                    mma16816(o[mt][2 * nt2 + 0], pah, tvl[nt2] + 0);
                    mma16816(o[mt][2 * nt2 + 1], pah, tvl[nt2] + 2);
                }
#pragma unroll
                for (int nt2 = 0; nt2 < 4; nt2++) {
                    mma16816(o[mt][2 * nt2 + 0], pal, tvh[nt2] + 0);
                    mma16816(o[mt][2 * nt2 + 1], pal, tvh[nt2] + 2);
                }
            }
        }
        // no trailing barrier: next iteration's top sync provides the fence
    }

    // ---- epilogue: ctx[b, s, h*64+dk] as bf16 hi/lo ----
    const int bb = bh >> 4;
    const int h  = bh & (H_ - 1);
#pragma unroll
    for (int mt = 0; mt < 2; mt++) {
        const float inv0 = 1.f / lsum[mt][0];
        const float inv1 = 1.f / lsum[mt][1];
        const int s0r = row_b + mt * 16;
#pragma unroll
        for (int nt = 0; nt < 8; nt++) {
            int dk = nt * 8 + 2 * (lane & 3);
            {
                float v0 = o[mt][nt][0] * inv0, v1 = o[mt][nt][1] * inv0;
                size_t idx = ((size_t)bb * S_ + s0r) * D_ + h * 64 + dk;
                uint32_t hp = pack2_hi(v0, v1);
                uint32_t lp = pack2_lo(v0, v1, hp);
                *(uint32_t*)&g_CH[idx] = hp;
                *(uint32_t*)&g_CL[idx] = lp;
            }
            {
                float v0 = o[mt][nt][2] * inv1, v1 = o[mt][nt][3] * inv1;
                size_t idx = ((size_t)bb * S_ + s0r + 8) * D_ + h * 64 + dk;
                uint32_t hp = pack2_hi(v0, v1);
                uint32_t lp = pack2_lo(v0, v1, hp);
                *(uint32_t*)&g_CH[idx] = hp;
                *(uint32_t*)&g_CL[idx] = lp;
            }
        }
    }
}

// ---------------------------------------------------------------------------
extern "C" void kernel_launch(void* const* d_in, const int* in_sizes, int n_in,
                              void* d_out, int out_size)
{
    const float* q  = (const float*)d_in[0];
    const float* k  = (const float*)d_in[1];
    const float* v  = (const float*)d_in[2];
    const float* Wq = (const float*)d_in[3];
    const float* Wk = (const float*)d_in[4];
    const float* Wv = (const float*)d_in[5];
    const float* Wo = (const float*)d_in[6];
    // d_in[7] = causal tril mask; applied analytically in flash_mma.
    float* out = (float*)d_out;

    cudaFuncSetAttribute(gemm_qkv, cudaFuncAttributeMaxDynamicSharedMemorySize, SMEM_GEMM);
    cudaFuncSetAttribute(gemm_out, cudaFuncAttributeMaxDynamicSharedMemorySize, SMEM_GEMM);
    cudaFuncSetAttribute(flash_mma, cudaFuncAttributeMaxDynamicSharedMemorySize, SMEM_FA);

    // 1. split all inputs to bf16 hi/lo
    split_act<<<dim3(M_ * D_ / 4 / 256, 1, 3), 256>>>(q, k, v);
    split_w<<<dim3(D_ * D_ / 4 / 256, 1, 4), 256>>>(Wq, Wk, Wv, Wo);

    // 2. Q/K/V projections in one launch (3072 CTAs, 2/SM)
    gemm_qkv<<<dim3(D_ / 128, M_ / 64, 3), 128, SMEM_GEMM>>>();

    // 3. causal flash attention (1024 CTAs, 2/SM, fat 32-row warps)
    flash_mma<<<dim3(S_ / 128, B_ * H_), 128, SMEM_FA>>>();

    // 4. output projection
    gemm_out<<<dim3(D_ / 128, M_ / 64), 128, SMEM_GEMM>>>(out);
}

// round 17
// speedup vs baseline: 1.4092x; 1.4032x over previous
#include <cuda_runtime.h>
#include <cuda_fp16.h>
#include <cstdint>
#include <math.h>

static constexpr int B_  = 4;
static constexpr int S_  = 2048;
static constexpr int D_  = 1024;
static constexpr int H_  = 16;
static constexpr int DK_ = 64;
static constexpr int M_  = B_ * S_;   // 8192 rows

// ---------------------------------------------------------------------------
// Scratch (allocation-free rule: __device__ globals). All fp16.
// ---------------------------------------------------------------------------
__device__ __half g_XH[3][(size_t)M_ * D_];   // q,k,v activation hi
__device__ __half g_XL[3][(size_t)M_ * D_];   // q,k,v activation lo
__device__ __half g_W16[4][(size_t)D_ * D_];  // Wq,Wk,Wv,Wo single fp16
__device__ __half g_QH[(size_t)M_ * D_];      // Q hi [B,H,S,DK] (scaled)
__device__ __half g_QL[(size_t)M_ * D_];      // Q lo
__device__ __half g_KH[(size_t)M_ * D_];      // K hi
__device__ __half g_KL[(size_t)M_ * D_];      // K lo
__device__ __half g_V16[(size_t)M_ * D_];     // V single fp16
__device__ __half g_CH[(size_t)M_ * D_];      // ctx hi [B,S,H*DK]
__device__ __half g_CL[(size_t)M_ * D_];      // ctx lo

// ---------------------------------------------------------------------------
// Warp-MMA helpers (base sm_80 features — valid on plain sm_103 PTX target)
// ---------------------------------------------------------------------------
__device__ __forceinline__ uint32_t smem_u32(const void* p) {
    uint32_t a;
    asm("{ .reg .u64 t; cvta.to.shared.u64 t, %1; cvt.u32.u64 %0, t; }"
        : "=r"(a) : "l"(p));
    return a;
}

__device__ __forceinline__ void cp16(uint32_t dst, const void* src) {
    asm volatile("cp.async.cg.shared.global [%0], [%1], 16;"
                 :: "r"(dst), "l"(src));
}
#define CP_COMMIT() asm volatile("cp.async.commit_group;" ::: "memory")
#define CP_WAIT(N)  asm volatile("cp.async.wait_group %0;" :: "n"(N) : "memory")

__device__ __forceinline__ void ldsm4(uint32_t* r, uint32_t addr) {
    asm volatile("ldmatrix.sync.aligned.m8n8.x4.shared.b16 {%0,%1,%2,%3}, [%4];"
                 : "=r"(r[0]), "=r"(r[1]), "=r"(r[2]), "=r"(r[3]) : "r"(addr));
}
__device__ __forceinline__ void ldsm4t(uint32_t* r, uint32_t addr) {
    asm volatile("ldmatrix.sync.aligned.m8n8.x4.trans.shared.b16 {%0,%1,%2,%3}, [%4];"
                 : "=r"(r[0]), "=r"(r[1]), "=r"(r[2]), "=r"(r[3]) : "r"(addr));
}

// fp16 MMA, fp32 accumulate
__device__ __forceinline__ void mma16816(float* c, const uint32_t* a,
                                         const uint32_t* b) {
    asm volatile(
        "mma.sync.aligned.m16n8k16.row.col.f32.f16.f16.f32 "
        "{%0,%1,%2,%3}, {%4,%5,%6,%7}, {%8,%9}, {%0,%1,%2,%3};"
        : "+f"(c[0]), "+f"(c[1]), "+f"(c[2]), "+f"(c[3])
        : "r"(a[0]), "r"(a[1]), "r"(a[2]), "r"(a[3]), "r"(b[0]), "r"(b[1]));
}

__device__ __forceinline__ uint32_t sw128(uint32_t b) { return b ^ ((b >> 3) & 0x70); }

__device__ __forceinline__ uint32_t pk2_hi(float c0, float c1) {
    __half2 p = __floats2half2_rn(c0, c1);
    return *(uint32_t*)&p;
}
__device__ __forceinline__ uint32_t pk2_lo(float c0, float c1, uint32_t hipack) {
    __half2 hp = *(__half2*)&hipack;
    __half2 p  = __floats2half2_rn(c0 - __half2float(hp.x),
                                   c1 - __half2float(hp.y));
    return *(uint32_t*)&p;
}

// ---------------------------------------------------------------------------
// Input conversions: activations -> fp16 hi/lo (z=0..2), weights -> fp16 (z=0..3)
// ---------------------------------------------------------------------------
__global__ __launch_bounds__(256) void split_act16(const float* __restrict__ q,
                                                   const float* __restrict__ k,
                                                   const float* __restrict__ v)
{
    int z = blockIdx.z;
    const float* src = (z == 0) ? q : (z == 1) ? k : v;
    int i = blockIdx.x * blockDim.x + threadIdx.x;
    float4 x = ((const float4*)src)[i];
    uint32_t h0 = pk2_hi(x.x, x.y);
    uint32_t h1 = pk2_hi(x.z, x.w);
    uint32_t l0 = pk2_lo(x.x, x.y, h0);
    uint32_t l1 = pk2_lo(x.z, x.w, h1);
    ((uint32_t*)g_XH[z])[2 * i + 0] = h0;
    ((uint32_t*)g_XH[z])[2 * i + 1] = h1;
    ((uint32_t*)g_XL[z])[2 * i + 0] = l0;
    ((uint32_t*)g_XL[z])[2 * i + 1] = l1;
}

__global__ __launch_bounds__(256) void conv_w16(const float* __restrict__ wq,
                                                const float* __restrict__ wk,
                                                const float* __restrict__ wv,
                                                const float* __restrict__ wo)
{
    int z = blockIdx.z;
    const float* src = (z == 0) ? wq : (z == 1) ? wk : (z == 2) ? wv : wo;
    int i = blockIdx.x * blockDim.x + threadIdx.x;
    float4 x = ((const float4*)src)[i];
    ((uint32_t*)g_W16[z])[2 * i + 0] = pk2_hi(x.x, x.y);
    ((uint32_t*)g_W16[z])[2 * i + 1] = pk2_hi(x.z, x.w);
}

// ---------------------------------------------------------------------------
// fp16 2-pass GEMM mainloop: c += X̂ @ Ŵ^T over K=1024 (X split hi/lo, W single).
// CTA 64x128, 4 warps, K-chunk 64, 2-stage cp.async, stage = 32KB => 64KB smem
// => 3 CTAs/SM. Error: 2^-12 from Ŵ rounding (absolute, random-sign averaged).
// ---------------------------------------------------------------------------
static constexpr int GA_T      = 8192;             // A tile 64x64 fp16
static constexpr int GB_T      = 16384;            // W tile 128x64 fp16
static constexpr int G_STAGE   = 2 * GA_T + GB_T;  // Ahi, Alo, W = 32 KB
static constexpr int SMEM_GEMM = 2 * G_STAGE;      // 64 KB

__device__ __forceinline__ void gemm_mainloop(
    const uint4* __restrict__ gAh, const uint4* __restrict__ gAl,
    const uint4* __restrict__ gW,
    int m0, int n0, uint32_t sb, float c[4][4][4])
{
    const int tid  = threadIdx.x;
    const int lane = tid & 31;
    const int wid  = tid >> 5;        // 0..3 = n quarter

    const int a_r = lane & 15;
    const int a_c = (lane >> 4) * 16;
    const int b_r = wid * 32 + (lane & 7) + ((lane >> 4) << 3);
    const int b_c = ((lane >> 3) & 1) * 16;

#pragma unroll
    for (int i = 0; i < 4; i++)
#pragma unroll
        for (int j = 0; j < 4; j++)
#pragma unroll
            for (int e = 0; e < 4; e++) c[i][j][e] = 0.f;

    auto load_chunk = [&](int kc, int stage) {
        const uint32_t sbase = sb + stage * G_STAGE;
        // A hi+lo: 1024 uint4, 8/thread
#pragma unroll
        for (int u = 0; u < 8; u++) {
            int fi   = u * 128 + tid;
            int tile = fi >> 9;              // 0=Ahi 1=Alo
            int e    = fi & 511;
            int row  = e >> 3;
            int j    = e & 7;
            uint32_t dst = sbase + tile * GA_T + sw128(row * 128 + j * 16);
            size_t gi = (size_t)(m0 + row) * 128 + kc * 8 + j;
            cp16(dst, (tile == 0 ? gAh : gAl) + gi);
        }
        // W: 1024 uint4, 8/thread
#pragma unroll
        for (int u = 0; u < 8; u++) {
            int fi  = u * 128 + tid;
            int row = fi >> 3;
            int j   = fi & 7;
            uint32_t dst = sbase + 2 * GA_T + sw128(row * 128 + j * 16);
            size_t gi = (size_t)(n0 + row) * 128 + kc * 8 + j;
            cp16(dst, gW + gi);
        }
    };

    load_chunk(0, 0); CP_COMMIT();

    for (int kc = 0; kc < 16; kc++) {
        if (kc < 15) { load_chunk(kc + 1, (kc + 1) & 1); CP_COMMIT(); CP_WAIT(1); }
        else         { CP_WAIT(0); }
        __syncthreads();

        const uint32_t st  = sb + (kc & 1) * G_STAGE;
        const uint32_t sAh = st;
        const uint32_t sAl = st + GA_T;
        const uint32_t sB  = st + 2 * GA_T;

#pragma unroll
        for (int ks = 0; ks < 4; ks++) {
            uint32_t bh[4][2];
#pragma unroll
            for (int nt2 = 0; nt2 < 2; nt2++) {
                uint32_t off = sw128((uint32_t)(b_r + nt2 * 16) * 128 + ks * 32 + b_c);
                uint32_t t[4];
                ldsm4(t, sB + off);
                bh[2 * nt2][0] = t[0]; bh[2 * nt2][1] = t[1];
                bh[2 * nt2 + 1][0] = t[2]; bh[2 * nt2 + 1][1] = t[3];
            }
#pragma unroll
            for (int mt = 0; mt < 4; mt++) {
                uint32_t off = sw128((uint32_t)(a_r + mt * 16) * 128 + ks * 32 + a_c);
                uint32_t ah[4], al[4];
                ldsm4(ah, sAh + off);
                ldsm4(al, sAl + off);
#pragma unroll
                for (int nt = 0; nt < 4; nt++) mma16816(c[mt][nt], ah, bh[nt]);
#pragma unroll
                for (int nt = 0; nt < 4; nt++) mma16816(c[mt][nt], al, bh[nt]);
            }
        }
        __syncthreads();
    }
}

// ---- QKV projections in one launch: grid (8, 128, 3) ----
__global__ __launch_bounds__(128, 3)
void gemm_qkv()
{
    extern __shared__ __align__(1024) char smem[];
    const uint32_t sb = smem_u32(smem);
    const int z  = blockIdx.z;
    const int n0 = blockIdx.x * 128;
    const int m0 = blockIdx.y * 64;
    // Q: fold 1/sqrt(dk)=0.125 AND log2(e) (exp2 softmax) into scale
    const float scale = (z == 0) ? 0.125f * 1.44269504f : 1.0f;

    float c[4][4][4];
    gemm_mainloop((const uint4*)g_XH[z], (const uint4*)g_XL[z],
                  (const uint4*)g_W16[z], m0, n0, sb, c);

    const int lane = threadIdx.x & 31;
    const int wid  = threadIdx.x >> 5;

#pragma unroll
    for (int mt = 0; mt < 4; mt++) {
#pragma unroll
        for (int half = 0; half < 2; half++) {
            int r  = m0 + mt * 16 + (lane >> 2) + half * 8;
            int bb = r >> 11;
            int s  = r & (S_ - 1);
#pragma unroll
            for (int nt = 0; nt < 4; nt++) {
                int e  = n0 + wid * 32 + nt * 8 + (lane & 3) * 2;
                int h  = e >> 6;
                int dk = e & 63;
                float v0 = c[mt][nt][2 * half + 0] * scale;
                float v1 = c[mt][nt][2 * half + 1] * scale;
                size_t idx = (((size_t)bb * H_ + h) * S_ + s) * DK_ + dk;
                uint32_t hp = pk2_hi(v0, v1);
                if (z == 0) {
                    *(uint32_t*)&g_QH[idx] = hp;
                    *(uint32_t*)&g_QL[idx] = pk2_lo(v0, v1, hp);
                } else if (z == 1) {
                    *(uint32_t*)&g_KH[idx] = hp;
                    *(uint32_t*)&g_KL[idx] = pk2_lo(v0, v1, hp);
                } else {
                    *(uint32_t*)&g_V16[idx] = hp;   // V single fp16
                }
            }
        }
    }
}

// ---- Output projection: ctx @ Wo^T -> fp32 out ----
__global__ __launch_bounds__(128, 3)
void gemm_out(float* __restrict__ Y)
{
    extern __shared__ __align__(1024) char smem[];
    const uint32_t sb = smem_u32(smem);
    const int n0 = blockIdx.x * 128;
    const int m0 = blockIdx.y * 64;

    float c[4][4][4];
    gemm_mainloop((const uint4*)g_CH, (const uint4*)g_CL,
                  (const uint4*)g_W16[3], m0, n0, sb, c);

    const int lane = threadIdx.x & 31;
    const int wid  = threadIdx.x >> 5;

#pragma unroll
    for (int mt = 0; mt < 4; mt++) {
#pragma unroll
        for (int half = 0; half < 2; half++) {
            int r = m0 + mt * 16 + (lane >> 2) + half * 8;
#pragma unroll
            for (int nt = 0; nt < 4; nt++) {
                int e = n0 + wid * 32 + nt * 8 + (lane & 3) * 2;
                size_t idx = (size_t)r * D_ + e;
                *(float2*)&Y[idx] = make_float2(c[mt][nt][2 * half + 0],
                                                c[mt][nt][2 * half + 1]);
            }
        }
    }
}

// ---------------------------------------------------------------------------
// Tensor-core causal flash attention (fp16 mixed precision).
// QK: Q hi/lo x K hi/lo, 3 passes (scores ~exact). PV: P hi/lo x V single,
// 2 passes (error 2^-12 from V rounding). CTA = 64 queries, 4 warps x 16 rows,
// key blocks of 64, 2-stage pipeline, one barrier/block. smem = 16K(Q) +
// 2 x 24K(Khi,Klo,V) = 64KB => 3 CTAs/SM. No-max base-2 softmax.
// ---------------------------------------------------------------------------
static constexpr int FA_T     = 8192;                // one 64x64 fp16 matrix
static constexpr int FA_KV0   = 2 * FA_T;            // Q hi+lo = 16KB
static constexpr int FA_STAGE = 3 * FA_T;            // Khi,Klo,V = 24KB
static constexpr int SMEM_FA  = FA_KV0 + 2 * FA_STAGE;   // 65536 (64KB)

__global__ __launch_bounds__(128, 3)
void flash_mma()
{
    extern __shared__ __align__(1024) char smem[];
    const uint32_t sb = smem_u32(smem);

    const int tid  = threadIdx.x;
    const int lane = tid & 31;
    const int wid  = tid >> 5;
    const int qb   = (gridDim.x - 1) - blockIdx.x;   // heavy tiles first
    const int bh   = blockIdx.y;

    const size_t head4 = (size_t)bh * S_ * DK_ / 8;
    const uint4* q4h = (const uint4*)g_QH + head4;
    const uint4* q4l = (const uint4*)g_QL + head4;
    const uint4* k4h = (const uint4*)g_KH + head4;
    const uint4* k4l = (const uint4*)g_KL + head4;
    const uint4* v4  = (const uint4*)g_V16 + head4;

    // ---- Q tile (64 x 64 fp16, hi+lo = 1024 uint4, 8/thread) ----
#pragma unroll
    for (int u = 0; u < 8; u++) {
        int fi   = u * 128 + tid;
        int tile = fi >> 9;              // 0=hi 1=lo
        int e    = fi & 511;
        int row  = e >> 3;
        int j    = e & 7;
        uint32_t dst = sb + tile * FA_T + sw128(row * 128 + j * 16);
        size_t gi = (size_t)(qb * 64 + row) * 8 + j;
        cp16(dst, (tile == 0 ? q4h : q4l) + gi);
    }
    CP_COMMIT();

    auto load_kv = [&](int kb, int st) {
        const uint32_t sbase = sb + FA_KV0 + st * FA_STAGE;
#pragma unroll
        for (int u = 0; u < 12; u++) {
            int fi   = u * 128 + tid;     // 0..1535
            int tile = fi >> 9;           // 0=Khi 1=Klo 2=V
            int e    = fi & 511;
            int row  = e >> 3;
            int j    = e & 7;
            uint32_t dst = sbase + tile * FA_T + sw128(row * 128 + j * 16);
            size_t gi = (size_t)(kb * 64 + row) * 8 + j;
            const uint4* src = (tile == 0) ? k4h : (tile == 1) ? k4l : v4;
            cp16(dst, src + gi);
        }
    };

    const int nkb = qb + 1;
    load_kv(0, 0); CP_COMMIT();

    const int a_r  = wid * 16 + (lane & 15);
    const int a_c  = (lane >> 4) * 16;
    const int b_r  = (lane & 7) + ((lane >> 4) << 3);
    const int b_c  = ((lane >> 3) & 1) * 16;
    const int vt_r = ((lane >> 3) & 1) * 8 + (lane & 7);
    const int vt_c = (lane >> 4) * 16;
    const uint32_t sQh = sb;
    const uint32_t sQl = sb + FA_T;

    float o[8][4];
#pragma unroll
    for (int nt = 0; nt < 8; nt++)
#pragma unroll
        for (int e = 0; e < 4; e++) o[nt][e] = 0.f;
    float l0 = 0.f, l1 = 0.f;

    const int row_g0 = qb * 64 + wid * 16 + (lane >> 2);

    for (int kb = 0; kb < nkb; kb++) {
        CP_WAIT(0);
        __syncthreads();       // fences kb-1 compute; stage (kb+1)&1 now free
        if (kb + 1 < nkb) { load_kv(kb + 1, (kb + 1) & 1); CP_COMMIT(); }

        const uint32_t st  = sb + FA_KV0 + (kb & 1) * FA_STAGE;
        const uint32_t sKh = st;
        const uint32_t sKl = st + FA_T;
        const uint32_t sV  = st + 2 * FA_T;

        // ---- scores: QK 3-pass (hh + hl + lh), 16 rows x 64 keys ----
        float sc[8][4];
#pragma unroll
        for (int nt = 0; nt < 8; nt++)
#pragma unroll
            for (int e = 0; e < 4; e++) sc[nt][e] = 0.f;

#pragma unroll
        for (int ks = 0; ks < 4; ks++) {
            uint32_t aoff = sw128((uint32_t)a_r * 128 + ks * 32 + a_c);
            uint32_t ah[4], al[4];
            ldsm4(ah, sQh + aoff);
            ldsm4(al, sQl + aoff);
            uint32_t th[4][4], tl[4][4];
#pragma unroll
            for (int nt2 = 0; nt2 < 4; nt2++) {
                uint32_t boff = sw128((uint32_t)(b_r + nt2 * 16) * 128 + ks * 32 + b_c);
                ldsm4(th[nt2], sKh + boff);
                ldsm4(tl[nt2], sKl + boff);
            }
#pragma unroll
            for (int nt2 = 0; nt2 < 4; nt2++) {
                mma16816(sc[2 * nt2 + 0], ah, th[nt2] + 0);
                mma16816(sc[2 * nt2 + 1], ah, th[nt2] + 2);
            }
#pragma unroll
            for (int nt2 = 0; nt2 < 4; nt2++) {
                mma16816(sc[2 * nt2 + 0], ah, tl[nt2] + 0);
                mma16816(sc[2 * nt2 + 1], ah, tl[nt2] + 2);
            }
#pragma unroll
            for (int nt2 = 0; nt2 < 4; nt2++) {
                mma16816(sc[2 * nt2 + 0], al, th[nt2] + 0);
                mma16816(sc[2 * nt2 + 1], al, th[nt2] + 2);
            }
        }

        // ---- causal mask (diagonal block only): exp2(-1e30) = 0 ----
        if (kb == qb) {
#pragma unroll
            for (int nt = 0; nt < 8; nt++) {
                int col = kb * 64 + nt * 8 + 2 * (lane & 3);
                if (col     > row_g0)     sc[nt][0] = -1e30f;
                if (col + 1 > row_g0)     sc[nt][1] = -1e30f;
                if (col     > row_g0 + 8) sc[nt][2] = -1e30f;
                if (col + 1 > row_g0 + 8) sc[nt][3] = -1e30f;
            }
        }

        // ---- softmax: p = exp2(s) (log2e pre-folded into Q); tree sums ----
#pragma unroll
        for (int nt = 0; nt < 8; nt++) {
            sc[nt][0] = exp2f(sc[nt][0]);
            sc[nt][1] = exp2f(sc[nt][1]);
            sc[nt][2] = exp2f(sc[nt][2]);
            sc[nt][3] = exp2f(sc[nt][3]);
        }
        {
            float a0 = 0.f, a1 = 0.f, b0 = 0.f, b1 = 0.f;
#pragma unroll
            for (int nt = 0; nt < 8; nt += 2) {
                a0 += sc[nt][0] + sc[nt][1];
                a1 += sc[nt + 1][0] + sc[nt + 1][1];
                b0 += sc[nt][2] + sc[nt][3];
                b1 += sc[nt + 1][2] + sc[nt + 1][3];
            }
            float rs0 = a0 + a1;
            float rs1 = b0 + b1;
            rs0 += __shfl_xor_sync(0xffffffffu, rs0, 1);
            rs0 += __shfl_xor_sync(0xffffffffu, rs0, 2);
            rs1 += __shfl_xor_sync(0xffffffffu, rs1, 1);
            rs1 += __shfl_xor_sync(0xffffffffu, rs1, 2);
            l0 += rs0;
            l1 += rs1;
        }

        // ---- O += P @ V : P hi/lo fp16 (packed on the fly), V single ----
#pragma unroll
        for (int ks = 0; ks < 4; ks++) {
            uint32_t tv[4][4];
#pragma unroll
            for (int nt2 = 0; nt2 < 4; nt2++) {
                uint32_t voff = sw128((uint32_t)(ks * 16 + vt_r) * 128 + nt2 * 32 + vt_c);
                ldsm4t(tv[nt2], sV + voff);
            }
            uint32_t pah[4], pal[4];
            pah[0] = pk2_hi(sc[2 * ks][0],     sc[2 * ks][1]);
            pah[1] = pk2_hi(sc[2 * ks][2],     sc[2 * ks][3]);
            pah[2] = pk2_hi(sc[2 * ks + 1][0], sc[2 * ks + 1][1]);
            pah[3] = pk2_hi(sc[2 * ks + 1][2], sc[2 * ks + 1][3]);
            pal[0] = pk2_lo(sc[2 * ks][0],     sc[2 * ks][1],     pah[0]);
            pal[1] = pk2_lo(sc[2 * ks][2],     sc[2 * ks][3],     pah[1]);
            pal[2] = pk2_lo(sc[2 * ks + 1][0], sc[2 * ks + 1][1], pah[2]);
            pal[3] = pk2_lo(sc[2 * ks + 1][2], sc[2 * ks + 1][3], pah[3]);
#pragma unroll
            for (int nt2 = 0; nt2 < 4; nt2++) {
                mma16816(o[2 * nt2 + 0], pah, tv[nt2] + 0);
                mma16816(o[2 * nt2 + 1], pah, tv[nt2] + 2);
            }
#pragma unroll
            for (int nt2 = 0; nt2 < 4; nt2++) {
                mma16816(o[2 * nt2 + 0], pal, tv[nt2] + 0);
                mma16816(o[2 * nt2 + 1], pal, tv[nt2] + 2);
            }
        }
        // no trailing barrier: next iteration's top sync provides the fence
    }

    // ---- epilogue: ctx[b, s, h*64+dk] as fp16 hi/lo ----
    const int bb = bh >> 4;
    const int h  = bh & (H_ - 1);
    const float inv0 = 1.f / l0;
    const float inv1 = 1.f / l1;
    const int s0r = qb * 64 + wid * 16 + (lane >> 2);
#pragma unroll
    for (int nt = 0; nt < 8; nt++) {
        int dk = nt * 8 + 2 * (lane & 3);
        {
            float v0 = o[nt][0] * inv0, v1 = o[nt][1] * inv0;
            size_t idx = ((size_t)bb * S_ + s0r) * D_ + h * 64 + dk;
            uint32_t hp = pk2_hi(v0, v1);
            *(uint32_t*)&g_CH[idx] = hp;
            *(uint32_t*)&g_CL[idx] = pk2_lo(v0, v1, hp);
        }
        {
            float v0 = o[nt][2] * inv1, v1 = o[nt][3] * inv1;
            size_t idx = ((size_t)bb * S_ + s0r + 8) * D_ + h * 64 + dk;
            uint32_t hp = pk2_hi(v0, v1);
            *(uint32_t*)&g_CH[idx] = hp;
            *(uint32_t*)&g_CL[idx] = pk2_lo(v0, v1, hp);
        }
    }
}

// ---------------------------------------------------------------------------
extern "C" void kernel_launch(void* const* d_in, const int* in_sizes, int n_in,
                              void* d_out, int out_size)
{
    const float* q  = (const float*)d_in[0];
    const float* k  = (const float*)d_in[1];
    const float* v  = (const float*)d_in[2];
    const float* Wq = (const float*)d_in[3];
    const float* Wk = (const float*)d_in[4];
    const float* Wv = (const float*)d_in[5];
    const float* Wo = (const float*)d_in[6];
    // d_in[7] = causal tril mask; applied analytically in flash_mma.
    float* out = (float*)d_out;

    cudaFuncSetAttribute(gemm_qkv, cudaFuncAttributeMaxDynamicSharedMemorySize, SMEM_GEMM);
    cudaFuncSetAttribute(gemm_out, cudaFuncAttributeMaxDynamicSharedMemorySize, SMEM_GEMM);
    cudaFuncSetAttribute(flash_mma, cudaFuncAttributeMaxDynamicSharedMemorySize, SMEM_FA);

    // 1. convert inputs: activations -> fp16 hi/lo, weights -> fp16
    split_act16<<<dim3(M_ * D_ / 4 / 256, 1, 3), 256>>>(q, k, v);
    conv_w16<<<dim3(D_ * D_ / 4 / 256, 1, 4), 256>>>(Wq, Wk, Wv, Wo);

    // 2. Q/K/V projections in one launch (3072 CTAs, 3/SM)
    gemm_qkv<<<dim3(D_ / 128, M_ / 64, 3), 128, SMEM_GEMM>>>();

    // 3. causal flash attention (2048 CTAs, 3/SM)
    flash_mma<<<dim3(S_ / 64, B_ * H_), 128, SMEM_FA>>>();

    // 4. output projection
    gemm_out<<<dim3(D_ / 128, M_ / 64), 128, SMEM_GEMM>>>(out);
}